// round 9
// baseline (speedup 1.0000x reference)
#include <cuda_runtime.h>
#include <cuda_bf16.h>
#include <stdint.h>

#define Bn 2
#define Sn 512
#define Hn 768
#define En 64
#define Mn 64
#define Rn 128
#define SIZE_E 32
#define CLS_ID 101
#define REP_K (2*Hn + SIZE_E)    /* 1568 */
#define REL_K (3*Hn + 2*SIZE_E)  /* 2368 */
#define NEGV (-1e30f)
#define NSPLIT 4

// ------------------------- device scratch -------------------------
__device__ float d_ctx[Bn*Hn];
__device__ float d_ppool[768*4*Hn];
__device__ int   d_pany[768*4];
__device__ float d_pool_ent[Bn*En*Hn];
__device__ float d_pool_men[Bn*Mn*Hn];
__device__ float d_rep_ner[Bn*En*REP_K];
__device__ float d_rep_emd[Bn*Mn*REP_K];
__device__ float d_repr_rel[Bn*Rn*REL_K];
__device__ float d_repr_cr [Bn*Rn*REL_K];
__device__ float d_cpart[2359296];       // stage0: 8 x 98304 ; stage1/2: 8 x 196608
__device__ float d_hid_ner[128*Hn];
__device__ float d_hid_emd[128*Hn];
__device__ float d_h1_rel[256*Hn];
__device__ float d_h1_cr [256*Hn];
__device__ float d_h2_rel[256*Hn];
__device__ float d_h2_cr [256*Hn];

#define S0_ELEM (128*Hn)       /* 98304 */
#define S1_BASE 786432
#define S1_ELEM (256*Hn)       /* 196608 */

// ------------------------- helpers -------------------------
__device__ __forceinline__ uint32_t smem_u32(const void* p) {
    uint32_t r;
    asm("{ .reg .u64 t; cvta.to.shared.u64 t, %1; cvt.u32.u64 %0, t; }" : "=r"(r) : "l"(p));
    return r;
}
__device__ __forceinline__ void ldsm4(uint32_t addr, uint32_t& r0, uint32_t& r1,
                                      uint32_t& r2, uint32_t& r3) {
    asm volatile("ldmatrix.sync.aligned.m8n8.x4.shared.b16 {%0,%1,%2,%3}, [%4];"
                 : "=r"(r0), "=r"(r1), "=r"(r2), "=r"(r3) : "r"(addr));
}
__device__ __forceinline__ void mma16816(float* d, const uint32_t* a, uint32_t b0, uint32_t b1) {
    asm volatile("mma.sync.aligned.m16n8k16.row.col.f32.bf16.bf16.f32 "
        "{%0,%1,%2,%3}, {%4,%5,%6,%7}, {%8,%9}, {%0,%1,%2,%3};"
        : "+f"(d[0]), "+f"(d[1]), "+f"(d[2]), "+f"(d[3])
        : "r"(a[0]), "r"(a[1]), "r"(a[2]), "r"(a[3]), "r"(b0), "r"(b1));
}
__device__ __forceinline__ void cvt_store(uint32_t phi, uint32_t plo, float4 v)
{
    __nv_bfloat162 hx = __floats2bfloat162_rn(v.x, v.y);
    __nv_bfloat162 hz = __floats2bfloat162_rn(v.z, v.w);
    float2 fx = __bfloat1622float2(hx);
    float2 fz = __bfloat1622float2(hz);
    __nv_bfloat162 lx = __floats2bfloat162_rn(v.x - fx.x, v.y - fx.y);
    __nv_bfloat162 lz = __floats2bfloat162_rn(v.z - fz.x, v.w - fz.y);
    uint32_t h0 = *(uint32_t*)&hx, h1 = *(uint32_t*)&hz;
    uint32_t l0 = *(uint32_t*)&lx, l1 = *(uint32_t*)&lz;
    asm volatile("st.shared.v2.b32 [%0], {%1, %2};" :: "r"(phi), "r"(h0), "r"(h1) : "memory");
    asm volatile("st.shared.v2.b32 [%0], {%1, %2};" :: "r"(plo), "r"(l0), "r"(l1) : "memory");
}

// ------------------------- pooled masked max (+ ctx blocks at end) -------------------------
__global__ __launch_bounds__(192) void pool_kernel(
    const int* __restrict__ em, const int* __restrict__ mm,
    const int* __restrict__ rm, const int* __restrict__ fm,
    const int* __restrict__ input_ids,
    const float* __restrict__ emb)
{
    int blk = blockIdx.x;
    if (blk >= 192) {
        int b = blk - 192;
        __shared__ int cidx;
        if (threadIdx.x == 0) cidx = Sn;
        __syncthreads();
        for (int s = threadIdx.x; s < Sn; s += blockDim.x)
            if (input_ids[b*Sn + s] == CLS_ID) atomicMin(&cidx, s);
        __syncthreads();
        int ci = (cidx == Sn) ? 0 : cidx;
        for (int h = threadIdx.x; h < Hn; h += blockDim.x)
            d_ctx[b*Hn + h] = emb[((size_t)b*Sn + ci)*Hn + h];
        return;
    }
    const int* masks; int Kspans, sgbase, local;
    if (blk < 32)       { masks = em; Kspans = En; sgbase = 0;   local = blk; }
    else if (blk < 64)  { masks = mm; Kspans = Mn; sgbase = 128; local = blk - 32; }
    else if (blk < 128) { masks = rm; Kspans = Rn; sgbase = 256; local = blk - 64; }
    else                { masks = fm; Kspans = Rn; sgbase = 512; local = blk - 128; }

    int gpb   = Kspans >> 4;
    int b     = local / (gpb*4);
    int rem   = local % (gpb*4);
    int g     = rem >> 2;
    int chunk = rem & 3;
    int s0    = chunk * 128;
    int k0    = g * 16;
    int sg0   = sgbase + b*Kspans + k0;

    __shared__ unsigned mw[128];
    __shared__ unsigned anyw;
    int tid = threadIdx.x;
    if (tid < 128) mw[tid] = 0u;
    if (tid == 0) anyw = 0u;
    __syncthreads();

    for (int i = tid; i < 16*128; i += 192) {
        int t = i >> 7, sl = i & 127;
        if (masks[(size_t)(b*Kspans + k0 + t)*Sn + s0 + sl] != 0)
            atomicOr(&mw[sl], 1u << t);
    }
    __syncthreads();

    unsigned aw = 0u;
    for (int sl = tid; sl < 128; sl += 192) aw |= mw[sl];
    if (aw) atomicOr(&anyw, aw);
    __syncthreads();

    int h0 = tid * 4;
    float4 acc[16];
    #pragma unroll
    for (int t = 0; t < 16; t++) acc[t] = make_float4(NEGV, NEGV, NEGV, NEGV);

    const float* ebase = emb + ((size_t)b*Sn + s0)*Hn + h0;
    for (int sl = 0; sl < 128; sl++) {
        float4 v = *(const float4*)(ebase + (size_t)sl*Hn);
        unsigned m = mw[sl];
        #pragma unroll
        for (int t = 0; t < 16; t++) {
            if (m & (1u << t)) {
                acc[t].x = fmaxf(acc[t].x, v.x);
                acc[t].y = fmaxf(acc[t].y, v.y);
                acc[t].z = fmaxf(acc[t].z, v.z);
                acc[t].w = fmaxf(acc[t].w, v.w);
            }
        }
    }
    unsigned a = anyw;
    #pragma unroll
    for (int t = 0; t < 16; t++)
        *(float4*)&d_ppool[((size_t)(sg0 + t)*4 + chunk)*Hn + h0] = acc[t];
    if (tid < 16) d_pany[(sg0 + tid)*4 + chunk] = (a >> tid) & 1u;
}

// ------------------------- combine partial maxes -------------------------
__global__ void combine_kernel()
{
    int span = blockIdx.x;
    int h0 = threadIdx.x * 4;
    float4 v = make_float4(NEGV, NEGV, NEGV, NEGV);
    #pragma unroll
    for (int c = 0; c < 4; c++) {
        float4 p = *(const float4*)&d_ppool[((size_t)span*4 + c)*Hn + h0];
        v.x = fmaxf(v.x, p.x); v.y = fmaxf(v.y, p.y);
        v.z = fmaxf(v.z, p.z); v.w = fmaxf(v.w, p.w);
    }
    int any = d_pany[span*4] | d_pany[span*4+1] | d_pany[span*4+2] | d_pany[span*4+3];

    float* out; bool zero_if_empty = false;
    if (span < 128)      out = d_pool_ent + (size_t)span*Hn;
    else if (span < 256) out = d_pool_men + (size_t)(span-128)*Hn;
    else if (span < 512) { out = d_repr_rel + (size_t)(span-256)*REL_K; zero_if_empty = true; }
    else                 { out = d_repr_cr  + (size_t)(span-512)*REL_K; zero_if_empty = true; }

    if (zero_if_empty && !any) v = make_float4(0.f, 0.f, 0.f, 0.f);
    *(float4*)(out + h0) = v;
}

// ------------------------- assemble representation rows -------------------------
__global__ void assemble_kernel(
    const int* __restrict__ entity_sizes, const int* __restrict__ mention_sizes,
    const int* __restrict__ relations,    const int* __restrict__ references,
    const float* __restrict__ ner_size_emb, const float* __restrict__ emd_size_emb)
{
    int row = blockIdx.x;
    int tid = threadIdx.x;
    if (row < 256) {
        bool ner = (row < 128);
        int r = ner ? row : row - 128;
        int b = r >> 6;
        const float* pool = (ner ? d_pool_ent : d_pool_men) + (size_t)r*Hn;
        int sz = (ner ? entity_sizes : mention_sizes)[r];
        const float* se = (ner ? ner_size_emb : emd_size_emb) + (size_t)sz*SIZE_E;
        float* dst = (ner ? d_rep_ner : d_rep_emd) + (size_t)r*REP_K;
        for (int i = tid; i < REP_K/4; i += 256) {
            int c = i * 4; float4 v;
            if (c < Hn)            v = *(const float4*)(d_ctx + b*Hn + c);
            else if (c < 2*Hn)     v = *(const float4*)(pool + c - Hn);
            else                   v = *(const float4*)(se + c - 2*Hn);
            *(float4*)(dst + c) = v;
        }
    } else {
        bool isrel = (row < 512);
        int r = isrel ? row - 256 : row - 512;
        int b = r >> 7;
        const int*   idxs  = isrel ? relations : references;
        const int*   szs   = isrel ? entity_sizes : mention_sizes;
        const float* semb  = isrel ? ner_size_emb : emd_size_emb;
        const float* poolb = isrel ? d_pool_ent : d_pool_men;
        int e1 = idxs[r*2], e2 = idxs[r*2 + 1];
        const float* p1 = poolb + (size_t)(b*64 + e1)*Hn;
        const float* p2 = poolb + (size_t)(b*64 + e2)*Hn;
        const float* s1 = semb + (size_t)szs[b*64 + e1]*SIZE_E;
        const float* s2 = semb + (size_t)szs[b*64 + e2]*SIZE_E;
        float* dst = (isrel ? d_repr_rel : d_repr_cr) + (size_t)r*REL_K + Hn;
        for (int i = tid; i < (REL_K - Hn)/4; i += 256) {
            int c = i * 4; float4 v;
            if (c < Hn)                  v = *(const float4*)(p1 + c);
            else if (c < 2*Hn)           v = *(const float4*)(p2 + c - Hn);
            else if (c < 2*Hn + SIZE_E)  v = *(const float4*)(s1 + c - 2*Hn);
            else                         v = *(const float4*)(s2 + c - 2*Hn - SIZE_E);
            *(float4*)(dst + c) = v;
        }
    }
}

// ------------------------- HMMA GEMM, lean 2-CTA/SM version -------------------------
#define PADK 72
#define OFF_AHI 0
#define OFF_ALO (128*PADK*2)
#define OFF_BHI (2*128*PADK*2)
#define OFF_BLO (OFF_BHI + 64*PADK*2)
#define BUFSZ   (OFF_BLO + 64*PADK*2)   /* 55296 */

struct Frag {
    uint32_t ah[2][4], al[2][4], bh[2][4], bl[2][4];
};

__device__ __forceinline__ void load_frag(Frag& f, uint32_t base, int k0,
                                          int wm, int wn, int rA, int cAo, int rB, int cBo)
{
    #pragma unroll
    for (int mi = 0; mi < 2; mi++) {
        uint32_t oa = (uint32_t)((wm*32 + mi*16 + rA) * PADK + k0 + cAo) * 2;
        ldsm4(base + OFF_AHI + oa, f.ah[mi][0], f.ah[mi][1], f.ah[mi][2], f.ah[mi][3]);
        ldsm4(base + OFF_ALO + oa, f.al[mi][0], f.al[mi][1], f.al[mi][2], f.al[mi][3]);
    }
    #pragma unroll
    for (int bi = 0; bi < 2; bi++) {
        uint32_t ob = (uint32_t)((wn*32 + bi*16 + rB) * PADK + k0 + cBo) * 2;
        ldsm4(base + OFF_BHI + ob, f.bh[bi][0], f.bh[bi][1], f.bh[bi][2], f.bh[bi][3]);
        ldsm4(base + OFF_BLO + ob, f.bl[bi][0], f.bl[bi][1], f.bl[bi][2], f.bl[bi][3]);
    }
}

__device__ __forceinline__ void do_mma(float acc[2][4][4], const Frag& f)
{
    #pragma unroll
    for (int mi = 0; mi < 2; mi++)
        #pragma unroll
        for (int ni = 0; ni < 4; ni++) {
            int bi = ni >> 1, p = (ni & 1) * 2;
            mma16816(acc[mi][ni], f.ah[mi], f.bh[bi][p], f.bh[bi][p+1]);
            mma16816(acc[mi][ni], f.ah[mi], f.bl[bi][p], f.bl[bi][p+1]);
            mma16816(acc[mi][ni], f.al[mi], f.bh[bi][p], f.bh[bi][p+1]);
        }
}

__global__ __launch_bounds__(256, 2) void gemm_mma_kernel(
    const float* __restrict__ Wa, const float* __restrict__ Wb,
    const float* __restrict__ Wc, const float* __restrict__ Wd,
    int mode)
{
    extern __shared__ char smem[];
    uint32_t sb = smem_u32(smem);
    int tid = threadIdx.x;
    int wid = tid >> 5, lane = tid & 31;
    int wm = wid & 3, wn = wid >> 2;

    // resolve job (NSPLIT=4)
    const float* A; const float* W; float* Out;
    int K, m0, n0, c0, c1;
    int bx = blockIdx.x;
    if (mode == 0 && bx < 96) {
        // stage0: 2 probs x 12 n-tiles x 4 splits
        int prob = bx / 48, r = bx % 48, nt = r >> 2, sp = r & 3;
        A = prob ? d_rep_emd : d_rep_ner;
        W = prob ? Wb : Wa;
        Out = d_cpart + (size_t)(prob*NSPLIT + sp) * S0_ELEM;
        K = REP_K; m0 = 0; n0 = nt * 64;
        int nc = (K + 63) >> 6;
        c0 = sp * nc / NSPLIT; c1 = (sp + 1) * nc / NSPLIT;
    } else {
        // stage1 (mode0, 192 CTAs) or stage2 (mode1, 192 CTAs):
        // 2 probs x 2 m-tiles x 12 n-tiles x 4 splits
        int i = (mode == 0) ? bx - 96 : bx;
        int prob = i / 96, r = i % 96;
        int mt = r / 48, r2 = r % 48, nt = r2 >> 2, sp = r2 & 3;
        if (mode == 0) {
            A = prob ? d_repr_cr : d_repr_rel;
            W = prob ? Wd : Wc; K = REL_K;
            Out = d_cpart + S1_BASE + (size_t)(prob*NSPLIT + sp) * S1_ELEM;
        } else {
            A = prob ? d_h1_cr : d_h1_rel;
            W = prob ? Wb : Wa; K = Hn;
            Out = d_cpart + S1_BASE + (size_t)(prob*NSPLIT + sp) * S1_ELEM;
        }
        m0 = mt * 128; n0 = nt * 64;
        int nc = (K + 63) >> 6;
        c0 = sp * nc / NSPLIT; c1 = (sp + 1) * nc / NSPLIT;
    }

    int row_ld = tid >> 4, c4_ld = (tid & 15) << 2;
    uint32_t o_st = (uint32_t)(row_ld * PADK + c4_ld) * 2;

    float acc[2][4][4];
    #pragma unroll
    for (int mi = 0; mi < 2; mi++)
        #pragma unroll
        for (int ni = 0; ni < 4; ni++)
            #pragma unroll
            for (int q = 0; q < 4; q++) acc[mi][ni][q] = 0.f;

    int g = lane >> 3;
    int rA = (lane & 7) + ((g & 1) << 3);
    int cAo = (g & 2) << 2;
    int rB = (lane & 7) + ((g & 2) << 2);
    int cBo = (g & 1) << 3;

    Frag f0;

    for (int c = c0; c < c1; c++) {
        int kc = K - (c << 6); if (kc > 64) kc = 64;
        uint32_t base = sb + (uint32_t)(c & 1) * BUFSZ;
        int kb = c << 6;

        // load + convert + store chunk c (co-resident CTA covers this phase)
        #pragma unroll
        for (int i = 0; i < 8; i++) {
            float4 v = *(const float4*)(A + (size_t)(m0 + row_ld + i*16)*K + kb + c4_ld);
            cvt_store(base + OFF_AHI + o_st + i*16*PADK*2,
                      base + OFF_ALO + o_st + i*16*PADK*2, v);
        }
        #pragma unroll
        for (int i = 0; i < 4; i++) {
            float4 v = *(const float4*)(W + (size_t)(n0 + row_ld + i*16)*K + kb + c4_ld);
            cvt_store(base + OFF_BHI + o_st + i*16*PADK*2,
                      base + OFF_BLO + o_st + i*16*PADK*2, v);
        }
        __syncthreads();   // one barrier per chunk (double SMEM buffer => safe reuse)

        int steps = kc >> 4;
        #pragma unroll 4
        for (int s = 0; s < steps; s++) {
            load_frag(f0, base, s << 4, wm, wn, rA, cAo, rB, cBo);
            do_mma(acc, f0);
        }
    }

    // epilogue: raw partial store (bias/relu in finalize)
    int r0 = lane >> 2, cq = (lane & 3) * 2;
    #pragma unroll
    for (int mi = 0; mi < 2; mi++) {
        #pragma unroll
        for (int ni = 0; ni < 4; ni++) {
            int col = n0 + wn*32 + ni*8 + cq;
            int row = m0 + wm*32 + mi*16 + r0;
            float2 v0 = make_float2(acc[mi][ni][0], acc[mi][ni][1]);
            float2 v1 = make_float2(acc[mi][ni][2], acc[mi][ni][3]);
            *(float2*)(Out + (size_t)row * Hn + col) = v0;
            *(float2*)(Out + (size_t)(row + 8) * Hn + col) = v1;
        }
    }
}

// ------------------------- finalize A: stage0 + stage1 (sum 4 splits) ---------------------
__global__ void finalizeA_kernel(
    const float* __restrict__ b_ner, const float* __restrict__ b_emd,
    const float* __restrict__ b_rel, const float* __restrict__ b_cr)
{
    int prob = blockIdx.y;
    int idx = blockIdx.x * 256 + threadIdx.x;
    if (idx < S0_ELEM) {
        const float* p = d_cpart + (size_t)(prob*NSPLIT) * S0_ELEM + idx;
        float s = (p[0] + p[S0_ELEM]) + (p[2*S0_ELEM] + p[3*(size_t)S0_ELEM])
                + (prob ? b_emd : b_ner)[idx % Hn];
        (prob ? d_hid_emd : d_hid_ner)[idx] = fmaxf(s, 0.f);
    } else {
        int j = idx - S0_ELEM;
        if (j >= S1_ELEM) return;
        const float* p = d_cpart + S1_BASE + (size_t)(prob*NSPLIT) * S1_ELEM + j;
        float s = (p[0] + p[S1_ELEM]) + (p[2*(size_t)S1_ELEM] + p[3*(size_t)S1_ELEM])
                + (prob ? b_cr : b_rel)[j % Hn];
        (prob ? d_h1_cr : d_h1_rel)[j] = fmaxf(s, 0.f);
    }
}

// ------------------------- finalize B: stage2 (sum 4 splits) -------------------------
__global__ void finalizeB_kernel(
    const float* __restrict__ b_rel, const float* __restrict__ b_cr)
{
    int prob = blockIdx.y;
    int idx = blockIdx.x * 256 + threadIdx.x;
    if (idx >= S1_ELEM) return;
    const float* p = d_cpart + S1_BASE + (size_t)(prob*NSPLIT) * S1_ELEM + idx;
    float s = (p[0] + p[S1_ELEM]) + (p[2*(size_t)S1_ELEM] + p[3*(size_t)S1_ELEM])
            + (prob ? b_cr : b_rel)[idx % Hn];
    (prob ? d_h2_cr : d_h2_rel)[idx] = fmaxf(s, 0.f);
}

// ------------------------- heads -------------------------
__global__ void heads_kernel(
    const float* __restrict__ ner_hw, const float* __restrict__ ner_hb,
    const float* __restrict__ emd_hw, const float* __restrict__ emd_hb,
    const float* __restrict__ rel_w3, const float* __restrict__ rel_b3,
    const float* __restrict__ cr_w3,  const float* __restrict__ cr_b3,
    float* __restrict__ out)
{
    int gwarp = (blockIdx.x * blockDim.x + threadIdx.x) >> 5;
    int lane = threadIdx.x & 31;
    if (gwarp >= 3840) return;
    const float* A; const float* Wr; float bias;
    if (gwarp < 1280) {
        int r = gwarp / 10, n = gwarp % 10;
        A = d_hid_ner + (size_t)r*Hn; Wr = ner_hw + (size_t)n*Hn; bias = ner_hb[n];
    } else if (gwarp < 3328) {
        int i = gwarp - 1280; int r = i / 8, n = i % 8;
        A = d_h2_rel + (size_t)r*Hn; Wr = rel_w3 + (size_t)n*Hn; bias = rel_b3[n];
    } else if (gwarp < 3584) {
        int i = gwarp - 3328; int r = i / 2, n = i & 1;
        A = d_hid_emd + (size_t)r*Hn; Wr = emd_hw + (size_t)n*Hn; bias = emd_hb[n];
    } else {
        int i = gwarp - 3584;
        A = d_h2_cr + (size_t)i*Hn; Wr = cr_w3; bias = cr_b3[0];
    }
    float s = 0.f;
    for (int k = lane*4; k < Hn; k += 128) {
        float4 a = *(const float4*)(A + k);
        float4 w = *(const float4*)(Wr + k);
        s += a.x*w.x + a.y*w.y + a.z*w.z + a.w*w.w;
    }
    #pragma unroll
    for (int o = 16; o; o >>= 1) s += __shfl_xor_sync(0xffffffffu, s, o);
    if (lane == 0) out[gwarp] = s + bias;
}

// ------------------------- launch -------------------------
extern "C" void kernel_launch(void* const* d_in, const int* in_sizes, int n_in,
                              void* d_out, int out_size)
{
    const int*   input_ids       = (const int*)  d_in[0];
    const int*   entity_masks    = (const int*)  d_in[1];
    const int*   entity_sizes    = (const int*)  d_in[2];
    const int*   mention_masks   = (const int*)  d_in[3];
    const int*   mention_sizes   = (const int*)  d_in[4];
    const int*   relations       = (const int*)  d_in[5];
    const int*   rel_masks       = (const int*)  d_in[6];
    const int*   references      = (const int*)  d_in[7];
    const int*   references_masks= (const int*)  d_in[8];
    const float* emb             = (const float*)d_in[9];
    const float* ner_size_emb    = (const float*)d_in[10];
    const float* emd_size_emb    = (const float*)d_in[11];
    const float* ner_rep_w = (const float*)d_in[12]; const float* ner_rep_b = (const float*)d_in[13];
    const float* ner_head_w= (const float*)d_in[14]; const float* ner_head_b= (const float*)d_in[15];
    const float* emd_rep_w = (const float*)d_in[16]; const float* emd_rep_b = (const float*)d_in[17];
    const float* emd_head_w= (const float*)d_in[18]; const float* emd_head_b= (const float*)d_in[19];
    const float* rel_w1 = (const float*)d_in[20]; const float* rel_b1 = (const float*)d_in[21];
    const float* rel_w2 = (const float*)d_in[22]; const float* rel_b2 = (const float*)d_in[23];
    const float* rel_w3 = (const float*)d_in[24]; const float* rel_b3 = (const float*)d_in[25];
    const float* cr_w1  = (const float*)d_in[26]; const float* cr_b1  = (const float*)d_in[27];
    const float* cr_w2  = (const float*)d_in[28]; const float* cr_b2  = (const float*)d_in[29];
    const float* cr_w3  = (const float*)d_in[30]; const float* cr_b3  = (const float*)d_in[31];
    float* out = (float*)d_out;

    const int smem_bytes = 2 * BUFSZ;   // 110592 per CTA; 2 CTAs/SM = 221184 <= 228KB carveout
    cudaFuncSetAttribute(gemm_mma_kernel, cudaFuncAttributeMaxDynamicSharedMemorySize, smem_bytes);

    pool_kernel<<<194, 192>>>(entity_masks, mention_masks, rel_masks, references_masks,
                              input_ids, emb);
    combine_kernel<<<768, 192>>>();
    assemble_kernel<<<768, 256>>>(entity_sizes, mention_sizes, relations, references,
                                  ner_size_emb, emd_size_emb);

    // launch 1: stage0 split-K4 (96 CTAs) + stage1 split-K4 (192 CTAs) = 288 CTAs (~2/SM)
    gemm_mma_kernel<<<288, 256, smem_bytes>>>(ner_rep_w, emd_rep_w, rel_w1, cr_w1, 0);
    {
        dim3 f((S0_ELEM + S1_ELEM + 255)/256, 2);
        finalizeA_kernel<<<f, 256>>>(ner_rep_b, emd_rep_b, rel_b1, cr_b1);
    }

    // launch 2: stage2 split-K4 (192 CTAs)
    gemm_mma_kernel<<<192, 256, smem_bytes>>>(rel_w2, cr_w2, nullptr, nullptr, 1);
    {
        dim3 f((S1_ELEM + 255)/256, 2);
        finalizeB_kernel<<<f, 256>>>(rel_b2, cr_b2);
    }

    heads_kernel<<<480, 256>>>(ner_head_w, ner_head_b, emd_head_w, emd_head_b,
                               rel_w3, rel_b3, cr_w3, cr_b3, out);
}

// round 10
// speedup vs baseline: 1.0782x; 1.0782x over previous
#include <cuda_runtime.h>
#include <cuda_bf16.h>
#include <stdint.h>

#define Bn 2
#define Sn 512
#define Hn 768
#define En 64
#define Mn 64
#define Rn 128
#define SIZE_E 32
#define CLS_ID 101
#define REP_K (2*Hn + SIZE_E)    /* 1568 */
#define REL_K (3*Hn + 2*SIZE_E)  /* 2368 */
#define NEGV (-1e30f)

// activation bf16 plane offsets (elements)
#define A_REP0  0
#define A_REP1  200704
#define A_REPR0 401408
#define A_REPR1 1007616
#define A_H1_0  1613824
#define A_H1_1  1810432
#define A_PLANE 2007040

// ------------------------- device scratch -------------------------
__device__ float d_ctx[Bn*Hn];
__device__ float d_ppool[768*4*Hn];
__device__ int   d_pany[768*4];
__device__ __nv_bfloat16 d_a_hi[A_PLANE];
__device__ __nv_bfloat16 d_a_lo[A_PLANE];
__device__ float d_cpart[2359296];       // stage0: 8 x 98304 @0 ; stage1: 8 x 196608 @786432 ; stage2 reuses @0
__device__ float d_hid_ner[128*Hn];
__device__ float d_hid_emd[128*Hn];
__device__ float d_h2_rel[256*Hn];
__device__ float d_h2_cr [256*Hn];

#define S0_ELEM (128*Hn)       /* 98304 */
#define S1_BASE 786432
#define S1_ELEM (256*Hn)       /* 196608 */

// ------------------------- helpers -------------------------
__device__ __forceinline__ uint32_t smem_u32(const void* p) {
    uint32_t r;
    asm("{ .reg .u64 t; cvta.to.shared.u64 t, %1; cvt.u32.u64 %0, t; }" : "=r"(r) : "l"(p));
    return r;
}
__device__ __forceinline__ void ldsm4(uint32_t addr, uint32_t& r0, uint32_t& r1,
                                      uint32_t& r2, uint32_t& r3) {
    asm volatile("ldmatrix.sync.aligned.m8n8.x4.shared.b16 {%0,%1,%2,%3}, [%4];"
                 : "=r"(r0), "=r"(r1), "=r"(r2), "=r"(r3) : "r"(addr));
}
__device__ __forceinline__ void mma16816(float* d, const uint32_t* a, uint32_t b0, uint32_t b1) {
    asm volatile("mma.sync.aligned.m16n8k16.row.col.f32.bf16.bf16.f32 "
        "{%0,%1,%2,%3}, {%4,%5,%6,%7}, {%8,%9}, {%0,%1,%2,%3};"
        : "+f"(d[0]), "+f"(d[1]), "+f"(d[2]), "+f"(d[3])
        : "r"(a[0]), "r"(a[1]), "r"(a[2]), "r"(a[3]), "r"(b0), "r"(b1));
}
// fp32x4 -> bf16 hi/lo pairs (uint2 each)
__device__ __forceinline__ void cvt_hilo(float4 v, uint2& h, uint2& l)
{
    __nv_bfloat162 hx = __floats2bfloat162_rn(v.x, v.y);
    __nv_bfloat162 hz = __floats2bfloat162_rn(v.z, v.w);
    float2 fx = __bfloat1622float2(hx);
    float2 fz = __bfloat1622float2(hz);
    __nv_bfloat162 lx = __floats2bfloat162_rn(v.x - fx.x, v.y - fx.y);
    __nv_bfloat162 lz = __floats2bfloat162_rn(v.z - fz.x, v.w - fz.y);
    h.x = *(uint32_t*)&hx; h.y = *(uint32_t*)&hz;
    l.x = *(uint32_t*)&lx; l.y = *(uint32_t*)&lz;
}
__device__ __forceinline__ void cvt_store(uint32_t phi, uint32_t plo, float4 v)
{
    uint2 h, l; cvt_hilo(v, h, l);
    asm volatile("st.shared.v2.b32 [%0], {%1, %2};" :: "r"(phi), "r"(h.x), "r"(h.y) : "memory");
    asm volatile("st.shared.v2.b32 [%0], {%1, %2};" :: "r"(plo), "r"(l.x), "r"(l.y) : "memory");
}
// max over 4 ppool chunks for one float4 of a span
__device__ __forceinline__ float4 pool_max4(int span, int cc)
{
    float4 v = *(const float4*)&d_ppool[((size_t)span*4 + 0)*Hn + cc];
    #pragma unroll
    for (int ch = 1; ch < 4; ch++) {
        float4 p = *(const float4*)&d_ppool[((size_t)span*4 + ch)*Hn + cc];
        v.x = fmaxf(v.x, p.x); v.y = fmaxf(v.y, p.y);
        v.z = fmaxf(v.z, p.z); v.w = fmaxf(v.w, p.w);
    }
    return v;
}

// ------------------------- pooled masked max (+ ctx blocks at end) -------------------------
__global__ __launch_bounds__(192) void pool_kernel(
    const int* __restrict__ em, const int* __restrict__ mm,
    const int* __restrict__ rm, const int* __restrict__ fm,
    const int* __restrict__ input_ids,
    const float* __restrict__ emb)
{
    int blk = blockIdx.x;
    if (blk >= 192) {
        int b = blk - 192;
        __shared__ int cidx;
        if (threadIdx.x == 0) cidx = Sn;
        __syncthreads();
        for (int s = threadIdx.x; s < Sn; s += blockDim.x)
            if (input_ids[b*Sn + s] == CLS_ID) atomicMin(&cidx, s);
        __syncthreads();
        int ci = (cidx == Sn) ? 0 : cidx;
        for (int h = threadIdx.x; h < Hn; h += blockDim.x)
            d_ctx[b*Hn + h] = emb[((size_t)b*Sn + ci)*Hn + h];
        return;
    }
    const int* masks; int Kspans, sgbase, local;
    if (blk < 32)       { masks = em; Kspans = En; sgbase = 0;   local = blk; }
    else if (blk < 64)  { masks = mm; Kspans = Mn; sgbase = 128; local = blk - 32; }
    else if (blk < 128) { masks = rm; Kspans = Rn; sgbase = 256; local = blk - 64; }
    else                { masks = fm; Kspans = Rn; sgbase = 512; local = blk - 128; }

    int gpb   = Kspans >> 4;
    int b     = local / (gpb*4);
    int rem   = local % (gpb*4);
    int g     = rem >> 2;
    int chunk = rem & 3;
    int s0    = chunk * 128;
    int k0    = g * 16;
    int sg0   = sgbase + b*Kspans + k0;

    __shared__ unsigned mw[128];
    __shared__ unsigned anyw;
    int tid = threadIdx.x;
    if (tid < 128) mw[tid] = 0u;
    if (tid == 0) anyw = 0u;
    __syncthreads();

    for (int i = tid; i < 16*128; i += 192) {
        int t = i >> 7, sl = i & 127;
        if (masks[(size_t)(b*Kspans + k0 + t)*Sn + s0 + sl] != 0)
            atomicOr(&mw[sl], 1u << t);
    }
    __syncthreads();

    unsigned aw = 0u;
    for (int sl = tid; sl < 128; sl += 192) aw |= mw[sl];
    if (aw) atomicOr(&anyw, aw);
    __syncthreads();

    int h0 = tid * 4;
    float4 acc[16];
    #pragma unroll
    for (int t = 0; t < 16; t++) acc[t] = make_float4(NEGV, NEGV, NEGV, NEGV);

    const float* ebase = emb + ((size_t)b*Sn + s0)*Hn + h0;
    for (int sl = 0; sl < 128; sl++) {
        float4 v = *(const float4*)(ebase + (size_t)sl*Hn);
        unsigned m = mw[sl];
        #pragma unroll
        for (int t = 0; t < 16; t++) {
            if (m & (1u << t)) {
                acc[t].x = fmaxf(acc[t].x, v.x);
                acc[t].y = fmaxf(acc[t].y, v.y);
                acc[t].z = fmaxf(acc[t].z, v.z);
                acc[t].w = fmaxf(acc[t].w, v.w);
            }
        }
    }
    unsigned a = anyw;
    #pragma unroll
    for (int t = 0; t < 16; t++)
        *(float4*)&d_ppool[((size_t)(sg0 + t)*4 + chunk)*Hn + h0] = acc[t];
    if (tid < 16) d_pany[(sg0 + tid)*4 + chunk] = (a >> tid) & 1u;
}

// ------------------------- assemble (combine fused in): write bf16 hi/lo planes --------------
__global__ void assemble_kernel(
    const int* __restrict__ entity_sizes, const int* __restrict__ mention_sizes,
    const int* __restrict__ relations,    const int* __restrict__ references,
    const float* __restrict__ ner_size_emb, const float* __restrict__ emd_size_emb)
{
    int row = blockIdx.x;
    int tid = threadIdx.x;
    if (row < 256) {
        int prob = row >> 7;           // 0 = ner, 1 = emd
        int r = row & 127;
        int b = r >> 6;
        int span = prob*128 + r;
        int sz = (prob ? mention_sizes : entity_sizes)[r];
        const float* se = (prob ? emd_size_emb : ner_size_emb) + (size_t)sz*SIZE_E;
        size_t off = (prob ? A_REP1 : A_REP0) + (size_t)r*REP_K;
        for (int i = tid; i < REP_K/4; i += 256) {
            int c = i * 4; float4 v;
            if (c < Hn)            v = *(const float4*)(d_ctx + b*Hn + c);
            else if (c < 2*Hn)     v = pool_max4(span, c - Hn);
            else                   v = *(const float4*)(se + c - 2*Hn);
            uint2 h, l; cvt_hilo(v, h, l);
            *(uint2*)&d_a_hi[off + c] = h;
            *(uint2*)&d_a_lo[off + c] = l;
        }
    } else {
        int isrel = (row < 512);
        int r = isrel ? row - 256 : row - 512;   // 0..255
        int b = r >> 7;
        int span_ctx = (isrel ? 256 : 512) + r;
        const int*   idxs  = isrel ? relations : references;
        const int*   szs   = isrel ? entity_sizes : mention_sizes;
        const float* semb  = isrel ? ner_size_emb : emd_size_emb;
        int pbase = isrel ? 0 : 128;
        int e1 = idxs[r*2], e2 = idxs[r*2 + 1];
        int span1 = pbase + b*64 + e1, span2 = pbase + b*64 + e2;
        const float* s1 = semb + (size_t)szs[b*64 + e1]*SIZE_E;
        const float* s2 = semb + (size_t)szs[b*64 + e2]*SIZE_E;
        int any = d_pany[span_ctx*4] | d_pany[span_ctx*4+1]
                | d_pany[span_ctx*4+2] | d_pany[span_ctx*4+3];
        size_t off = (isrel ? A_REPR0 : A_REPR1) + (size_t)r*REL_K;
        for (int i = tid; i < REL_K/4; i += 256) {
            int c = i * 4; float4 v;
            if (c < Hn) {
                v = pool_max4(span_ctx, c);
                if (!any) v = make_float4(0.f, 0.f, 0.f, 0.f);
            }
            else if (c < 2*Hn)            v = pool_max4(span1, c - Hn);
            else if (c < 3*Hn)            v = pool_max4(span2, c - 2*Hn);
            else if (c < 3*Hn + SIZE_E)   v = *(const float4*)(s1 + c - 3*Hn);
            else                          v = *(const float4*)(s2 + c - 3*Hn - SIZE_E);
            uint2 h, l; cvt_hilo(v, h, l);
            *(uint2*)&d_a_hi[off + c] = h;
            *(uint2*)&d_a_lo[off + c] = l;
        }
    }
}

// ------------------------- HMMA GEMM: A from bf16 planes, W fp32 cvt inline ----------------
#define PADK 72
#define OFF_AHI 0
#define OFF_ALO (128*PADK*2)
#define OFF_BHI (2*128*PADK*2)
#define OFF_BLO (OFF_BHI + 64*PADK*2)
#define BUFSZ   (OFF_BLO + 64*PADK*2)   /* 55296 */

struct Frag {
    uint32_t ah[2][4], al[2][4], bh[2][4], bl[2][4];
};

__device__ __forceinline__ void load_frag(Frag& f, uint32_t base, int k0,
                                          int wm, int wn, int rA, int cAo, int rB, int cBo)
{
    #pragma unroll
    for (int mi = 0; mi < 2; mi++) {
        uint32_t oa = (uint32_t)((wm*32 + mi*16 + rA) * PADK + k0 + cAo) * 2;
        ldsm4(base + OFF_AHI + oa, f.ah[mi][0], f.ah[mi][1], f.ah[mi][2], f.ah[mi][3]);
        ldsm4(base + OFF_ALO + oa, f.al[mi][0], f.al[mi][1], f.al[mi][2], f.al[mi][3]);
    }
    #pragma unroll
    for (int bi = 0; bi < 2; bi++) {
        uint32_t ob = (uint32_t)((wn*32 + bi*16 + rB) * PADK + k0 + cBo) * 2;
        ldsm4(base + OFF_BHI + ob, f.bh[bi][0], f.bh[bi][1], f.bh[bi][2], f.bh[bi][3]);
        ldsm4(base + OFF_BLO + ob, f.bl[bi][0], f.bl[bi][1], f.bl[bi][2], f.bl[bi][3]);
    }
}

__device__ __forceinline__ void do_mma(float acc[2][4][4], const Frag& f)
{
    #pragma unroll
    for (int mi = 0; mi < 2; mi++)
        #pragma unroll
        for (int ni = 0; ni < 4; ni++) {
            int bi = ni >> 1, p = (ni & 1) * 2;
            mma16816(acc[mi][ni], f.ah[mi], f.bh[bi][p], f.bh[bi][p+1]);
            mma16816(acc[mi][ni], f.ah[mi], f.bl[bi][p], f.bl[bi][p+1]);
            mma16816(acc[mi][ni], f.al[mi], f.bh[bi][p], f.bh[bi][p+1]);
        }
}

__global__ __launch_bounds__(256, 2) void gemm_mma_kernel(
    const float* __restrict__ Wa, const float* __restrict__ Wb,
    const float* __restrict__ Wc, const float* __restrict__ Wd,
    int mode)
{
    extern __shared__ char smem[];
    uint32_t sb = smem_u32(smem);
    int tid = threadIdx.x;
    int wid = tid >> 5, lane = tid & 31;
    int wm = wid & 3, wn = wid >> 2;

    // resolve job
    const __nv_bfloat16 *Ah, *Al; const float* W; float* Out;
    int K, m0, n0, c0, c1;
    int bx = blockIdx.x;
    if (mode == 0 && bx < 96) {
        // stage0: 2 probs x 12 n-tiles x 4 splits
        int prob = bx / 48, r = bx % 48, nt = r >> 2, sp = r & 3;
        size_t aoff = prob ? A_REP1 : A_REP0;
        Ah = d_a_hi + aoff; Al = d_a_lo + aoff;
        W = prob ? Wb : Wa;
        Out = d_cpart + (size_t)(prob*4 + sp) * S0_ELEM;
        K = REP_K; m0 = 0; n0 = nt * 64;
        int nc = (K + 63) >> 6;   // 25
        c0 = sp * nc / 4; c1 = (sp + 1) * nc / 4;
    } else if (mode == 0) {
        // stage1: 2 probs x 2 m-tiles x 12 n-tiles x 4 splits (192 CTAs)
        int i = bx - 96;
        int prob = i / 96, r = i % 96;
        int mt = r / 48, r2 = r % 48, nt = r2 >> 2, sp = r2 & 3;
        size_t aoff = prob ? A_REPR1 : A_REPR0;
        Ah = d_a_hi + aoff; Al = d_a_lo + aoff;
        W = prob ? Wd : Wc; K = REL_K;
        Out = d_cpart + S1_BASE + (size_t)(prob*4 + sp) * S1_ELEM;
        m0 = mt * 128; n0 = nt * 64;
        int nc = (K + 63) >> 6;   // 37
        c0 = sp * nc / 4; c1 = (sp + 1) * nc / 4;
    } else {
        // stage2: 2 probs x 2 m-tiles x 12 n-tiles x 2 splits (96 CTAs)
        int i = bx;
        int prob = i / 48, r = i % 48;
        int mt = r / 24, r2 = r % 24, nt = r2 >> 1, sp = r2 & 1;
        size_t aoff = prob ? A_H1_1 : A_H1_0;
        Ah = d_a_hi + aoff; Al = d_a_lo + aoff;
        W = prob ? Wb : Wa; K = Hn;
        Out = d_cpart + (size_t)(prob*2 + sp) * S1_ELEM;
        m0 = mt * 128; n0 = nt * 64;
        c0 = sp * 6; c1 = (sp + 1) * 6;   // 12 chunks / 2
    }

    float acc[2][4][4];
    #pragma unroll
    for (int mi = 0; mi < 2; mi++)
        #pragma unroll
        for (int ni = 0; ni < 4; ni++)
            #pragma unroll
            for (int q = 0; q < 4; q++) acc[mi][ni][q] = 0.f;

    int g = lane >> 3;
    int rA = (lane & 7) + ((g & 1) << 3);
    int cAo = (g & 2) << 2;
    int rB = (lane & 7) + ((g & 2) << 2);
    int cBo = (g & 1) << 3;

    int wrow_ld = tid >> 4, wc4_ld = (tid & 15) << 2;

    Frag f0;

    for (int c = c0; c < c1; c++) {
        int kc = K - (c << 6); if (kc > 64) kc = 64;
        uint32_t base = sb + (uint32_t)(c & 1) * BUFSZ;
        int kb = c << 6;

        // A chunk: bf16 hi/lo planes, plain uint4 copies (no conversion)
        #pragma unroll
        for (int i = 0; i < 4; i++) {
            int u = tid + (i << 8);
            int arow = u >> 3, c16 = u & 7;
            const __nv_bfloat16* ph = Ah + (size_t)(m0 + arow)*K + kb + c16*8;
            const __nv_bfloat16* pl = Al + (size_t)(m0 + arow)*K + kb + c16*8;
            uint4 vh = *(const uint4*)ph;
            uint4 vl = *(const uint4*)pl;
            uint32_t o = (uint32_t)arow * (PADK*2) + c16*16;
            asm volatile("st.shared.v4.b32 [%0], {%1,%2,%3,%4};"
                :: "r"(base + OFF_AHI + o), "r"(vh.x), "r"(vh.y), "r"(vh.z), "r"(vh.w) : "memory");
            asm volatile("st.shared.v4.b32 [%0], {%1,%2,%3,%4};"
                :: "r"(base + OFF_ALO + o), "r"(vl.x), "r"(vl.y), "r"(vl.z), "r"(vl.w) : "memory");
        }
        // W chunk: fp32 -> bf16 hi/lo inline
        #pragma unroll
        for (int i = 0; i < 4; i++) {
            int idx = tid + (i << 8);
            int wrow = (idx >> 4), c4 = (idx & 15) << 2;
            float4 v = *(const float4*)(W + (size_t)(n0 + wrow)*K + kb + c4);
            uint32_t o = (uint32_t)(wrow * PADK + c4) * 2;
            cvt_store(base + OFF_BHI + o, base + OFF_BLO + o, v);
        }
        __syncthreads();   // data ready; double buffer handles reuse

        int steps = kc >> 4;
        #pragma unroll 4
        for (int s = 0; s < steps; s++) {
            load_frag(f0, base, s << 4, wm, wn, rA, cAo, rB, cBo);
            do_mma(acc, f0);
        }
    }

    // epilogue: raw partial store (bias/relu in finalize)
    int r0 = lane >> 2, cq = (lane & 3) * 2;
    #pragma unroll
    for (int mi = 0; mi < 2; mi++) {
        #pragma unroll
        for (int ni = 0; ni < 4; ni++) {
            int col = n0 + wn*32 + ni*8 + cq;
            int row = m0 + wm*32 + mi*16 + r0;
            float2 v0 = make_float2(acc[mi][ni][0], acc[mi][ni][1]);
            float2 v1 = make_float2(acc[mi][ni][2], acc[mi][ni][3]);
            *(float2*)(Out + (size_t)row * Hn + col) = v0;
            *(float2*)(Out + (size_t)(row + 8) * Hn + col) = v1;
        }
    }
}

// ------------------------- finalize A: stage0 (fp32 hid) + stage1 (bf16 h1 planes) ----------
__global__ void finalizeA_kernel(
    const float* __restrict__ b_ner, const float* __restrict__ b_emd,
    const float* __restrict__ b_rel, const float* __restrict__ b_cr)
{
    int prob = blockIdx.y;
    int idx4 = (blockIdx.x * 256 + threadIdx.x) * 4;
    if (idx4 < S0_ELEM) {
        const float* p = d_cpart + (size_t)(prob*4) * S0_ELEM + idx4;
        float4 a = *(const float4*)p;
        float4 b = *(const float4*)(p + S0_ELEM);
        float4 c = *(const float4*)(p + 2*(size_t)S0_ELEM);
        float4 d = *(const float4*)(p + 3*(size_t)S0_ELEM);
        float4 bb = *(const float4*)((prob ? b_emd : b_ner) + (idx4 % Hn));
        float4 r;
        r.x = fmaxf((a.x + b.x) + (c.x + d.x) + bb.x, 0.f);
        r.y = fmaxf((a.y + b.y) + (c.y + d.y) + bb.y, 0.f);
        r.z = fmaxf((a.z + b.z) + (c.z + d.z) + bb.z, 0.f);
        r.w = fmaxf((a.w + b.w) + (c.w + d.w) + bb.w, 0.f);
        *(float4*)((prob ? d_hid_emd : d_hid_ner) + idx4) = r;
    } else {
        int j = idx4 - S0_ELEM;
        if (j >= S1_ELEM) return;
        const float* p = d_cpart + S1_BASE + (size_t)(prob*4) * S1_ELEM + j;
        float4 a = *(const float4*)p;
        float4 b = *(const float4*)(p + S1_ELEM);
        float4 c = *(const float4*)(p + 2*(size_t)S1_ELEM);
        float4 d = *(const float4*)(p + 3*(size_t)S1_ELEM);
        float4 bb = *(const float4*)((prob ? b_cr : b_rel) + (j % Hn));
        float4 r;
        r.x = fmaxf((a.x + b.x) + (c.x + d.x) + bb.x, 0.f);
        r.y = fmaxf((a.y + b.y) + (c.y + d.y) + bb.y, 0.f);
        r.z = fmaxf((a.z + b.z) + (c.z + d.z) + bb.z, 0.f);
        r.w = fmaxf((a.w + b.w) + (c.w + d.w) + bb.w, 0.f);
        uint2 h, l; cvt_hilo(r, h, l);
        size_t off = (prob ? A_H1_1 : A_H1_0) + j;
        *(uint2*)&d_a_hi[off] = h;
        *(uint2*)&d_a_lo[off] = l;
    }
}

// ------------------------- finalize B: stage2 (sum 2 splits, fp32 h2) -------------------------
__global__ void finalizeB_kernel(
    const float* __restrict__ b_rel, const float* __restrict__ b_cr)
{
    int prob = blockIdx.y;
    int idx4 = (blockIdx.x * 256 + threadIdx.x) * 4;
    if (idx4 >= S1_ELEM) return;
    const float* p = d_cpart + (size_t)(prob*2) * S1_ELEM + idx4;
    float4 a = *(const float4*)p;
    float4 b = *(const float4*)(p + S1_ELEM);
    float4 bb = *(const float4*)((prob ? b_cr : b_rel) + (idx4 % Hn));
    float4 r;
    r.x = fmaxf(a.x + b.x + bb.x, 0.f);
    r.y = fmaxf(a.y + b.y + bb.y, 0.f);
    r.z = fmaxf(a.z + b.z + bb.z, 0.f);
    r.w = fmaxf(a.w + b.w + bb.w, 0.f);
    *(float4*)((prob ? d_h2_cr : d_h2_rel) + idx4) = r;
}

// ------------------------- heads -------------------------
__global__ void heads_kernel(
    const float* __restrict__ ner_hw, const float* __restrict__ ner_hb,
    const float* __restrict__ emd_hw, const float* __restrict__ emd_hb,
    const float* __restrict__ rel_w3, const float* __restrict__ rel_b3,
    const float* __restrict__ cr_w3,  const float* __restrict__ cr_b3,
    float* __restrict__ out)
{
    int gwarp = (blockIdx.x * blockDim.x + threadIdx.x) >> 5;
    int lane = threadIdx.x & 31;
    if (gwarp >= 3840) return;
    const float* A; const float* Wr; float bias;
    if (gwarp < 1280) {
        int r = gwarp / 10, n = gwarp % 10;
        A = d_hid_ner + (size_t)r*Hn; Wr = ner_hw + (size_t)n*Hn; bias = ner_hb[n];
    } else if (gwarp < 3328) {
        int i = gwarp - 1280; int r = i / 8, n = i % 8;
        A = d_h2_rel + (size_t)r*Hn; Wr = rel_w3 + (size_t)n*Hn; bias = rel_b3[n];
    } else if (gwarp < 3584) {
        int i = gwarp - 3328; int r = i / 2, n = i & 1;
        A = d_hid_emd + (size_t)r*Hn; Wr = emd_hw + (size_t)n*Hn; bias = emd_hb[n];
    } else {
        int i = gwarp - 3584;
        A = d_h2_cr + (size_t)i*Hn; Wr = cr_w3; bias = cr_b3[0];
    }
    float s = 0.f;
    for (int k = lane*4; k < Hn; k += 128) {
        float4 a = *(const float4*)(A + k);
        float4 w = *(const float4*)(Wr + k);
        s += a.x*w.x + a.y*w.y + a.z*w.z + a.w*w.w;
    }
    #pragma unroll
    for (int o = 16; o; o >>= 1) s += __shfl_xor_sync(0xffffffffu, s, o);
    if (lane == 0) out[gwarp] = s + bias;
}

// ------------------------- launch -------------------------
extern "C" void kernel_launch(void* const* d_in, const int* in_sizes, int n_in,
                              void* d_out, int out_size)
{
    const int*   input_ids       = (const int*)  d_in[0];
    const int*   entity_masks    = (const int*)  d_in[1];
    const int*   entity_sizes    = (const int*)  d_in[2];
    const int*   mention_masks   = (const int*)  d_in[3];
    const int*   mention_sizes   = (const int*)  d_in[4];
    const int*   relations       = (const int*)  d_in[5];
    const int*   rel_masks       = (const int*)  d_in[6];
    const int*   references      = (const int*)  d_in[7];
    const int*   references_masks= (const int*)  d_in[8];
    const float* emb             = (const float*)d_in[9];
    const float* ner_size_emb    = (const float*)d_in[10];
    const float* emd_size_emb    = (const float*)d_in[11];
    const float* ner_rep_w = (const float*)d_in[12]; const float* ner_rep_b = (const float*)d_in[13];
    const float* ner_head_w= (const float*)d_in[14]; const float* ner_head_b= (const float*)d_in[15];
    const float* emd_rep_w = (const float*)d_in[16]; const float* emd_rep_b = (const float*)d_in[17];
    const float* emd_head_w= (const float*)d_in[18]; const float* emd_head_b= (const float*)d_in[19];
    const float* rel_w1 = (const float*)d_in[20]; const float* rel_b1 = (const float*)d_in[21];
    const float* rel_w2 = (const float*)d_in[22]; const float* rel_b2 = (const float*)d_in[23];
    const float* rel_w3 = (const float*)d_in[24]; const float* rel_b3 = (const float*)d_in[25];
    const float* cr_w1  = (const float*)d_in[26]; const float* cr_b1  = (const float*)d_in[27];
    const float* cr_w2  = (const float*)d_in[28]; const float* cr_b2  = (const float*)d_in[29];
    const float* cr_w3  = (const float*)d_in[30]; const float* cr_b3  = (const float*)d_in[31];
    float* out = (float*)d_out;

    const int smem_bytes = 2 * BUFSZ;   // 110592/CTA; 2 CTA/SM
    cudaFuncSetAttribute(gemm_mma_kernel, cudaFuncAttributeMaxDynamicSharedMemorySize, smem_bytes);

    pool_kernel<<<194, 192>>>(entity_masks, mention_masks, rel_masks, references_masks,
                              input_ids, emb);
    assemble_kernel<<<768, 256>>>(entity_sizes, mention_sizes, relations, references,
                                  ner_size_emb, emd_size_emb);

    // launch 1: stage0 split-K4 (96) + stage1 split-K4 (192) = 288 CTAs
    gemm_mma_kernel<<<288, 256, smem_bytes>>>(ner_rep_w, emd_rep_w, rel_w1, cr_w1, 0);
    {
        dim3 f((S0_ELEM + S1_ELEM)/1024, 2);
        finalizeA_kernel<<<f, 256>>>(ner_rep_b, emd_rep_b, rel_b1, cr_b1);
    }

    // launch 2: stage2 split-K2 (96 CTAs)
    gemm_mma_kernel<<<96, 256, smem_bytes>>>(rel_w2, cr_w2, nullptr, nullptr, 1);
    {
        dim3 f(S1_ELEM/1024, 2);
        finalizeB_kernel<<<f, 256>>>(rel_b2, cr_b2);
    }

    heads_kernel<<<480, 256>>>(ner_head_w, ner_head_b, emd_head_w, emd_head_b,
                               rel_w3, rel_b3, cr_w3, cr_b3, out);
}